// round 2
// baseline (speedup 1.0000x reference)
#include <cuda_runtime.h>
#include <math.h>

// ---------------- problem constants (fixed shapes) ----------------
#define S_TOK 6240
#define DIMM  1536
#define NH    12
#define HD    128
#define CHK   1560          // chunk = 30*52
#define NC    4             // number of chunks
#define LSEL  3120          // top_k(2) * CHK
#define NKT   25            // ceil(3120/128); last tile ragged (48 valid)
#define C1    22            // rope split: 64 - 2*(64/3)
#define C2    21

// ---------------- scratch (device globals: no cudaMalloc allowed) ----------------
__device__ float g_q[(size_t)S_TOK * DIMM];
__device__ float g_k[(size_t)S_TOK * DIMM];
__device__ float g_v[(size_t)S_TOK * DIMM];
__device__ float g_o[(size_t)S_TOK * DIMM];
__device__ float g_phiq[NH * HD];
__device__ float g_phik[NC * NH * HD];
__device__ int   g_idx[NH * 2];

// ======================================================================
// GEMM: C[M x 1536] = A[M x 1536] * B^T (B is [1536 x 1536] row-major) + bias
// 128x128 tile, BK=16, 256 threads, 8x8 per thread.
// ======================================================================
__global__ __launch_bounds__(256) void gemm_bias_kernel(
    const float* __restrict__ A, const float* __restrict__ B,
    const float* __restrict__ bias, float* __restrict__ C, int M)
{
    __shared__ float As[16][132];   // [k][m]
    __shared__ float Bs[16][132];   // [k][n]
    const int bm = blockIdx.y * 128;
    const int bn = blockIdx.x * 128;
    const int tid = threadIdx.x;
    const int tx = tid & 15;        // n dir
    const int ty = tid >> 4;        // m dir
    const int lr = tid >> 2;        // 0..63 load row
    const int lc = (tid & 3) * 4;   // 0,4,8,12 load col
    const bool full = (bm + 128 <= M);

    float acc[8][8];
#pragma unroll
    for (int i = 0; i < 8; i++)
#pragma unroll
        for (int j = 0; j < 8; j++) acc[i][j] = 0.f;

    for (int k0 = 0; k0 < DIMM; k0 += 16) {
#pragma unroll
        for (int h = 0; h < 2; ++h) {
            int r = lr + h * 64;
            int gr = bm + r;
            float4 av = make_float4(0.f, 0.f, 0.f, 0.f);
            if (full || gr < M) av = *(const float4*)(A + (size_t)gr * DIMM + k0 + lc);
            As[lc + 0][r] = av.x; As[lc + 1][r] = av.y;
            As[lc + 2][r] = av.z; As[lc + 3][r] = av.w;
            float4 bv = *(const float4*)(B + (size_t)(bn + r) * DIMM + k0 + lc);
            Bs[lc + 0][r] = bv.x; Bs[lc + 1][r] = bv.y;
            Bs[lc + 2][r] = bv.z; Bs[lc + 3][r] = bv.w;
        }
        __syncthreads();
#pragma unroll
        for (int kk = 0; kk < 16; ++kk) {
            float a[8], b[8];
            float4 t;
            t = *(const float4*)&As[kk][ty * 8];     a[0]=t.x; a[1]=t.y; a[2]=t.z; a[3]=t.w;
            t = *(const float4*)&As[kk][ty * 8 + 4]; a[4]=t.x; a[5]=t.y; a[6]=t.z; a[7]=t.w;
            t = *(const float4*)&Bs[kk][tx * 8];     b[0]=t.x; b[1]=t.y; b[2]=t.z; b[3]=t.w;
            t = *(const float4*)&Bs[kk][tx * 8 + 4]; b[4]=t.x; b[5]=t.y; b[6]=t.z; b[7]=t.w;
#pragma unroll
            for (int i = 0; i < 8; i++)
#pragma unroll
                for (int j = 0; j < 8; j++)
                    acc[i][j] += a[i] * b[j];
        }
        __syncthreads();
    }
#pragma unroll
    for (int i = 0; i < 8; i++) {
        int row = bm + ty * 8 + i;
        if (!full && row >= M) continue;
#pragma unroll
        for (int j = 0; j < 8; j++) {
            int col = bn + tx * 8 + j;
            C[(size_t)row * DIMM + col] = acc[i][j] + bias[col];
        }
    }
}

// ======================================================================
// Fused RMSNorm (over 1536) + 3D RoPE. grid = (S, 2): y=0 -> q, y=1 -> k.
// ======================================================================
__global__ __launch_bounds__(256) void norm_rope_kernel(
    float* __restrict__ q, float* __restrict__ k,
    const float* __restrict__ gq, const float* __restrict__ gk,
    const float* __restrict__ freqs)
{
    const int s = blockIdx.x;
    float* row = (blockIdx.y == 0 ? q : k) + (size_t)s * DIMM;
    const float* g = (blockIdx.y == 0 ? gq : gk);
    const int tid = threadIdx.x;

    float ss = 0.f;
#pragma unroll
    for (int i = 0; i < 6; i++) { float v = row[tid + i * 256]; ss += v * v; }
#pragma unroll
    for (int off = 16; off > 0; off >>= 1) ss += __shfl_xor_sync(0xffffffffu, ss, off);
    __shared__ float warp_s[8];
    __shared__ float total_s;
    if ((tid & 31) == 0) warp_s[tid >> 5] = ss;
    __syncthreads();
    if (tid == 0) {
        float t = 0.f;
#pragma unroll
        for (int i = 0; i < 8; i++) t += warp_s[i];
        total_s = t;
    }
    __syncthreads();
    const float scale = rsqrtf(total_s * (1.0f / DIMM) + 1e-6f);

    const int f  = s / CHK;
    const int rm = s % CHK;
    const int hh = rm / 52;
    const int ww = rm % 52;

    for (int p = tid; p < DIMM / 2; p += 256) {
        int d0 = 2 * p;
        float a = row[d0]     * scale * g[d0];
        float b = row[d0 + 1] * scale * g[d0 + 1];
        int jh = p & 63;   // pair index within head
        int pos = (jh < C1) ? f : ((jh < C1 + C2) ? hh : ww);
        float cv = freqs[(pos * 64 + jh) * 2 + 0];
        float sv = freqs[(pos * 64 + jh) * 2 + 1];
        row[d0]     = a * cv - b * sv;
        row[d0 + 1] = a * sv + b * cv;
    }
}

// ======================================================================
// phi means: blocks 0..47 -> phik[n][h][:], blocks 48..59 -> phiq[h][:]
// ======================================================================
__global__ void phi_kernel(const float* __restrict__ q, const float* __restrict__ k,
                           float* __restrict__ phiq, float* __restrict__ phik)
{
    int d = threadIdx.x;  // 128
    int b = blockIdx.x;
    if (b < NC * NH) {
        int n = b / NH, h = b % NH;
        float sum = 0.f;
        const float* base = k + (size_t)(n * CHK) * DIMM + h * HD + d;
        for (int r = 0; r < CHK; r++) sum += base[(size_t)r * DIMM];
        phik[(n * NH + h) * HD + d] = sum * (1.0f / CHK);
    } else {
        int h = b - NC * NH;
        float sum = 0.f;
        const float* base = q + h * HD + d;
        for (int r = 0; r < S_TOK; r++) sum += base[(size_t)r * DIMM];
        phiq[h * HD + d] = sum * (1.0f / S_TOK);
    }
}

// ======================================================================
// routing: per-head scores over 4 chunks, top-2, sorted ascending
// ======================================================================
__global__ void route_kernel(const float* __restrict__ phiq,
                             const float* __restrict__ phik, int* __restrict__ idx)
{
    int h = blockIdx.x;
    int lane = threadIdx.x;
    float sc[NC];
#pragma unroll
    for (int n = 0; n < NC; n++) {
        float p = 0.f;
        for (int d = lane; d < HD; d += 32)
            p += phiq[h * HD + d] * phik[(n * NH + h) * HD + d];
#pragma unroll
        for (int off = 16; off > 0; off >>= 1) p += __shfl_xor_sync(0xffffffffu, p, off);
        sc[n] = p;
    }
    if (lane == 0) {
        int i0 = 0;
        for (int n = 1; n < NC; n++) if (sc[n] > sc[i0]) i0 = n;
        int i1 = -1;
        for (int n = 0; n < NC; n++) {
            if (n == i0) continue;
            if (i1 < 0 || sc[n] > sc[i1]) i1 = n;
        }
        idx[h * 2 + 0] = min(i0, i1);
        idx[h * 2 + 1] = max(i0, i1);
    }
}

// ======================================================================
// Flash attention: per (q-tile 128, head). Keys gathered from 2 selected
// chunks. smem: Qt[d][r], KP (Kt[d][c] then reused as P[r][c]), Vs[j][d].
// MASKED template param: only the last key tile needs bounds masking.
// ======================================================================
#define SMEM_FLASH (3 * 128 * 132 * 4)

__device__ __forceinline__ void flash_tile_body(
    float* __restrict__ Qt, float* __restrict__ KP, float* __restrict__ Vs,
    const float* __restrict__ k, const float* __restrict__ v,
    int kb, int c0, int c1, int tx, int ty, int d0,
    float (&accO)[8][8], float (&m_i)[8], float (&l_i)[8], bool masked)
{
    const float scl = 0.08838834764831843f;  // 1/sqrt(128)
    __syncthreads();  // protect prev-iter P/V reads
    // load K (transposed) + V
#pragma unroll
    for (int p = 0; p < 8; p++) {
        int c = p * 16 + ty;
        int jg = kb + c;
        float4 kv0 = make_float4(0.f,0.f,0.f,0.f), kv1 = kv0, vv0 = kv0, vv1 = kv0;
        if (!masked || jg < LSEL) {
            int src = (jg < CHK) ? (c0 + jg) : (c1 + jg - CHK);
            const float* kp_ = k + (size_t)src * DIMM + d0;
            kv0 = *(const float4*)kp_;
            kv1 = *(const float4*)(kp_ + 4);
            const float* vp_ = v + (size_t)src * DIMM + d0;
            vv0 = *(const float4*)vp_;
            vv1 = *(const float4*)(vp_ + 4);
        }
        KP[(d0 + 0) * 132 + c] = kv0.x; KP[(d0 + 1) * 132 + c] = kv0.y;
        KP[(d0 + 2) * 132 + c] = kv0.z; KP[(d0 + 3) * 132 + c] = kv0.w;
        KP[(d0 + 4) * 132 + c] = kv1.x; KP[(d0 + 5) * 132 + c] = kv1.y;
        KP[(d0 + 6) * 132 + c] = kv1.z; KP[(d0 + 7) * 132 + c] = kv1.w;
        *(float4*)&Vs[c * 132 + d0]     = vv0;
        *(float4*)&Vs[c * 132 + d0 + 4] = vv1;
    }
    __syncthreads();

    // S = Q K^T
    float s8[8][8];
#pragma unroll
    for (int i = 0; i < 8; i++)
#pragma unroll
        for (int j = 0; j < 8; j++) s8[i][j] = 0.f;
#pragma unroll 8
    for (int kk = 0; kk < 128; kk++) {
        float a[8], b[8];
        float4 tt;
        tt = *(const float4*)&Qt[kk * 132 + ty * 8];     a[0]=tt.x; a[1]=tt.y; a[2]=tt.z; a[3]=tt.w;
        tt = *(const float4*)&Qt[kk * 132 + ty * 8 + 4]; a[4]=tt.x; a[5]=tt.y; a[6]=tt.z; a[7]=tt.w;
        tt = *(const float4*)&KP[kk * 132 + tx * 8];     b[0]=tt.x; b[1]=tt.y; b[2]=tt.z; b[3]=tt.w;
        tt = *(const float4*)&KP[kk * 132 + tx * 8 + 4]; b[4]=tt.x; b[5]=tt.y; b[6]=tt.z; b[7]=tt.w;
#pragma unroll
        for (int i = 0; i < 8; i++)
#pragma unroll
            for (int j = 0; j < 8; j++)
                s8[i][j] += a[i] * b[j];
    }

    // scale + (optional) mask + online softmax
    float mt[8];
#pragma unroll
    for (int i = 0; i < 8; i++) {
        float mx = -1e30f;
#pragma unroll
        for (int j = 0; j < 8; j++) {
            float val = s8[i][j] * scl;
            if (masked && (kb + tx * 8 + j >= LSEL)) val = -1e30f;
            s8[i][j] = val;
            mx = fmaxf(mx, val);
        }
#pragma unroll
        for (int off = 1; off < 16; off <<= 1)
            mx = fmaxf(mx, __shfl_xor_sync(0xffffffffu, mx, off));
        mt[i] = mx;
    }
#pragma unroll
    for (int i = 0; i < 8; i++) {
        float mn = fmaxf(m_i[i], mt[i]);
        float alpha = __expf(m_i[i] - mn);
        m_i[i] = mn;
        float r = 0.f;
#pragma unroll
        for (int j = 0; j < 8; j++) {
            float p_ = __expf(s8[i][j] - mn);
            s8[i][j] = p_;
            r += p_;
        }
#pragma unroll
        for (int off = 1; off < 16; off <<= 1)
            r += __shfl_xor_sync(0xffffffffu, r, off);
        l_i[i] = l_i[i] * alpha + r;
#pragma unroll
        for (int j = 0; j < 8; j++) accO[i][j] *= alpha;
    }

    __syncthreads();  // everyone done reading Kt
    // write P into KP as P[r][c]
#pragma unroll
    for (int i = 0; i < 8; i++) {
#pragma unroll
        for (int j = 0; j < 8; j++)
            KP[(ty * 8 + i) * 132 + tx * 8 + j] = s8[i][j];
    }
    __syncthreads();

    // O += P * V
#pragma unroll 8
    for (int kk = 0; kk < 128; kk++) {
        float a[8], b[8];
#pragma unroll
        for (int i = 0; i < 8; i++) a[i] = KP[(ty * 8 + i) * 132 + kk];
        float4 tt;
        tt = *(const float4*)&Vs[kk * 132 + tx * 8];     b[0]=tt.x; b[1]=tt.y; b[2]=tt.z; b[3]=tt.w;
        tt = *(const float4*)&Vs[kk * 132 + tx * 8 + 4]; b[4]=tt.x; b[5]=tt.y; b[6]=tt.z; b[7]=tt.w;
#pragma unroll
        for (int i = 0; i < 8; i++)
#pragma unroll
            for (int j = 0; j < 8; j++)
                accO[i][j] += a[i] * b[j];
    }
}

__global__ __launch_bounds__(256, 1) void flash_kernel(
    const float* __restrict__ q, const float* __restrict__ k,
    const float* __restrict__ v, const int* __restrict__ idx,
    float* __restrict__ o)
{
    extern __shared__ float sm[];
    float* Qt = sm;                  // [128][132]  (d-major)
    float* KP = sm + 128 * 132;      // Kt[d][c] / P[r][c]
    float* Vs = sm + 2 * 128 * 132;  // [j][d]

    const int h  = blockIdx.y;
    const int q0 = blockIdx.x * 128;
    const int tid = threadIdx.x;
    const int tx = tid & 15;
    const int ty = tid >> 4;
    const int d0 = tx * 8;
    const bool qfull = (q0 + 128 <= S_TOK);

    // load Q tile transposed
#pragma unroll
    for (int p = 0; p < 8; p++) {
        int r = p * 16 + ty;
        int gr = q0 + r;
        float4 v0 = make_float4(0.f,0.f,0.f,0.f), v1 = v0;
        if (qfull || gr < S_TOK) {
            const float* src = q + (size_t)gr * DIMM + h * HD + d0;
            v0 = *(const float4*)src;
            v1 = *(const float4*)(src + 4);
        }
        Qt[(d0 + 0) * 132 + r] = v0.x; Qt[(d0 + 1) * 132 + r] = v0.y;
        Qt[(d0 + 2) * 132 + r] = v0.z; Qt[(d0 + 3) * 132 + r] = v0.w;
        Qt[(d0 + 4) * 132 + r] = v1.x; Qt[(d0 + 5) * 132 + r] = v1.y;
        Qt[(d0 + 6) * 132 + r] = v1.z; Qt[(d0 + 7) * 132 + r] = v1.w;
    }
    const int c0 = idx[h * 2 + 0] * CHK;
    const int c1 = idx[h * 2 + 1] * CHK;
    const float* kh = k + h * HD;
    const float* vh = v + h * HD;

    float accO[8][8];
    float m_i[8], l_i[8];
#pragma unroll
    for (int i = 0; i < 8; i++) {
        m_i[i] = -1e30f; l_i[i] = 0.f;
#pragma unroll
        for (int j = 0; j < 8; j++) accO[i][j] = 0.f;
    }

    for (int t = 0; t < NKT - 1; ++t)
        flash_tile_body(Qt, KP, Vs, kh, vh, t * 128, c0, c1, tx, ty, d0,
                        accO, m_i, l_i, false);
    flash_tile_body(Qt, KP, Vs, kh, vh, (NKT - 1) * 128, c0, c1, tx, ty, d0,
                    accO, m_i, l_i, true);

    // epilogue
#pragma unroll
    for (int i = 0; i < 8; i++) {
        int row = q0 + ty * 8 + i;
        if (!qfull && row >= S_TOK) continue;
        float inv = 1.0f / l_i[i];
        float4 o0, o1;
        o0.x = accO[i][0] * inv; o0.y = accO[i][1] * inv;
        o0.z = accO[i][2] * inv; o0.w = accO[i][3] * inv;
        o1.x = accO[i][4] * inv; o1.y = accO[i][5] * inv;
        o1.z = accO[i][6] * inv; o1.w = accO[i][7] * inv;
        float* dst = o + (size_t)row * DIMM + h * HD + tx * 8;
        *(float4*)dst = o0;
        *(float4*)(dst + 4) = o1;
    }
}

// ======================================================================
extern "C" void kernel_launch(void* const* d_in, const int* in_sizes, int n_in,
                              void* d_out, int out_size)
{
    const float* x     = (const float*)d_in[0];
    const float* freqs = (const float*)d_in[3];
    const float* wq    = (const float*)d_in[4];
    const float* bq    = (const float*)d_in[5];
    const float* wk    = (const float*)d_in[6];
    const float* bk    = (const float*)d_in[7];
    const float* wv    = (const float*)d_in[8];
    const float* bv    = (const float*)d_in[9];
    const float* wo    = (const float*)d_in[10];
    const float* bo    = (const float*)d_in[11];
    const float* gq    = (const float*)d_in[12];
    const float* gk    = (const float*)d_in[13];
    float* out = (float*)d_out;

    float *qb, *kb, *vb, *ob, *phiq, *phik;
    int* idxp;
    cudaGetSymbolAddress((void**)&qb,   g_q);
    cudaGetSymbolAddress((void**)&kb,   g_k);
    cudaGetSymbolAddress((void**)&vb,   g_v);
    cudaGetSymbolAddress((void**)&ob,   g_o);
    cudaGetSymbolAddress((void**)&phiq, g_phiq);
    cudaGetSymbolAddress((void**)&phik, g_phik);
    cudaGetSymbolAddress((void**)&idxp, g_idx);

    dim3 gemm_grid(DIMM / 128, (S_TOK + 127) / 128);
    gemm_bias_kernel<<<gemm_grid, 256>>>(x, wq, bq, qb, S_TOK);
    gemm_bias_kernel<<<gemm_grid, 256>>>(x, wk, bk, kb, S_TOK);
    gemm_bias_kernel<<<gemm_grid, 256>>>(x, wv, bv, vb, S_TOK);

    norm_rope_kernel<<<dim3(S_TOK, 2), 256>>>(qb, kb, gq, gk, freqs);

    phi_kernel<<<NC * NH + NH, 128>>>(qb, kb, phiq, phik);
    route_kernel<<<NH, 32>>>(phiq, phik, idxp);

    cudaFuncSetAttribute(flash_kernel, cudaFuncAttributeMaxDynamicSharedMemorySize, SMEM_FLASH);
    flash_kernel<<<dim3((S_TOK + 127) / 128, NH), 256, SMEM_FLASH>>>(qb, kb, vb, idxp, ob);

    gemm_bias_kernel<<<gemm_grid, 256>>>(ob, wo, bo, out, S_TOK);
}